// round 1
// baseline (speedup 1.0000x reference)
#include <cuda_runtime.h>
#include <math.h>

// ---------------------------------------------------------------------------
// AdaptivePatchEmbedding
//   B=128, C=32, S=336 -> N=4096 sequences, R=7 regions of 48, TARGET=6
//   Experts: patch lens {8,16,24,48}, D_MODEL=512
//
// Forward value of gumbel-softmax straight-through == pure one-hot, so only
// the selected expert's embedding is computed per region. repeat_interleave
// duplicates rows: unique rows per region = {6,2,2,1} for p={8,16,24,48}.
//
// Pipeline: pe_init -> router(compact per-expert lists) -> 4x grouped GEMM.
// ---------------------------------------------------------------------------

#define NREG 28672            // 4096 * 7 regions
#define XP_ELEMS 88080384LL   // 4096 * 42 * 512

__device__ int   g_counts[4];
__device__ int   g_lists[4 * NREG];
__device__ float g_pe[42 * 512];

// --------------------------- stage 0: pe table + counter reset --------------
__global__ void __launch_bounds__(256) pe_init_kernel() {
    int i = blockIdx.x * 256 + threadIdx.x;
    if (i < 4) g_counts[i] = 0;
    if (i < 42 * 512) {
        int pos = i >> 9;
        int d   = i & 511;
        double dv  = exp((double)(d & ~1) * -(log(10000.0) / 512.0));
        double ang = (double)pos * dv;
        g_pe[i] = (float)((d & 1) ? cos(ang) : sin(ang));
    }
}

// --------------------------- stage 1: router --------------------------------
__global__ void __launch_bounds__(256) router_kernel(
    const float* __restrict__ x,  const float* __restrict__ un,
    const float* __restrict__ W1, const float* __restrict__ b1,
    const float* __restrict__ W2, const float* __restrict__ b2,
    float* __restrict__ out, int write_mode)
{
    __shared__ float W1s[48 * 64];
    __shared__ float W2s[256];
    __shared__ float b1s[64];
    int tid = threadIdx.x;
    for (int i = tid; i < 3072; i += 256) W1s[i] = W1[i];
    if (tid < 256) W2s[tid] = W2[tid];
    if (tid < 64)  b1s[tid] = b1[tid];
    __syncthreads();

    int region = blockIdx.x * 256 + tid;     // grid = 112 blocks -> exactly 28672
    int n = region / 7, r = region - n * 7;

    float xr[48];
    const float4* xp = (const float4*)x + n * 84 + r * 12;
#pragma unroll
    for (int v = 0; v < 12; v++) {
        float4 t = xp[v];
        xr[4*v+0] = t.x; xr[4*v+1] = t.y; xr[4*v+2] = t.z; xr[4*v+3] = t.w;
    }

    float lg0 = b2[0], lg1 = b2[1], lg2 = b2[2], lg3 = b2[3];
#pragma unroll 2
    for (int k = 0; k < 64; k++) {
        float s = b1s[k];
#pragma unroll
        for (int j = 0; j < 48; j++) s = fmaf(xr[j], W1s[j * 64 + k], s);
        s = fmaxf(s, 0.0f);
        lg0 = fmaf(s, W2s[k*4+0], lg0);
        lg1 = fmaf(s, W2s[k*4+1], lg1);
        lg2 = fmaf(s, W2s[k*4+2], lg2);
        lg3 = fmaf(s, W2s[k*4+3], lg3);
    }

    const float* up = un + (long long)region * 4;
    float z0 = lg0 - logf(-logf(up[0] + 1e-10f) + 1e-10f);
    float z1 = lg1 - logf(-logf(up[1] + 1e-10f) + 1e-10f);
    float z2 = lg2 - logf(-logf(up[2] + 1e-10f) + 1e-10f);
    float z3 = lg3 - logf(-logf(up[3] + 1e-10f) + 1e-10f);

    int e = 0; float best = z0;               // first-max semantics like jnp.argmax
    if (z1 > best) { best = z1; e = 1; }
    if (z2 > best) { best = z2; e = 2; }
    if (z3 > best) { best = z3; e = 3; }

    int slot = atomicAdd(&g_counts[e], 1);
    g_lists[e * NREG + slot] = region;

    // tail outputs: [x_patch (XP_ELEMS)] [C as f32] [cls_pred region-major]
    if (write_mode >= 2) out[XP_ELEMS + 1 + (long long)r * 4096 + n] = (float)e;
    if (write_mode >= 1 && region == 0) out[XP_ELEMS] = 32.0f;
}

// --------------------------- stage 2: per-expert grouped GEMM ---------------
// For patch length P: K_rep = 7 - 48/P, unique rows U = ceil(6/K_rep),
// unique row q covers t in [q*K_rep, min((q+1)*K_rep, 6)), segment xr[q*P : q*P+P].
// Block = 256 threads, 24 unique rows (RPB = 24/U regions), 512 cols.
// Thread (tx in [0,128), ty in {0,1}): 12 rows x 4 cols = 48 accumulators.
template<int P>
__global__ void __launch_bounds__(256) embed_kernel(
    const float4* __restrict__ x4, const float4* __restrict__ W4,
    float4* __restrict__ out4)
{
    constexpr int E   = (P == 8) ? 0 : (P == 16) ? 1 : (P == 24) ? 2 : 3;
    constexpr int K   = 7 - 48 / P;
    constexpr int U   = (6 + K - 1) / K;
    constexpr int RPB = 24 / U;

    extern __shared__ float sm[];
    float* Wsm = sm;                 // P * 512 floats
    float* xrs = sm + P * 512;       // RPB * 48 floats
    __shared__ int rids[24];

    int tid  = threadIdx.x;
    int cnt  = g_counts[E];
    int base = blockIdx.x * RPB;
    if (base >= cnt) return;
    int nval = min(RPB, cnt - base);

    for (int i = tid; i < P * 128; i += 256) ((float4*)Wsm)[i] = W4[i];
    if (tid < nval) rids[tid] = g_lists[E * NREG + base + tid];
    __syncthreads();

    for (int i = tid; i < nval * 12; i += 256) {
        int reg = i / 12, v = i - reg * 12;
        int rid = rids[reg];
        int n = rid / 7, r = rid - n * 7;
        ((float4*)xrs)[reg * 12 + v] = x4[n * 84 + r * 12 + v];
    }
    __syncthreads();

    int tx = tid & 127, ty = tid >> 7;

    // per-row smem base offsets (compile-time q per rr; row/U varies only by ty)
    int aoff[12];
#pragma unroll
    for (int rr = 0; rr < 12; rr++) {
        int row = ty * 12 + rr;
        aoff[rr] = (row / U) * 48 + (row % U) * P;
    }

    float4 acc[12];
#pragma unroll
    for (int i = 0; i < 12; i++) acc[i] = make_float4(0.f, 0.f, 0.f, 0.f);

    const float4* Wsm4 = (const float4*)Wsm;
#pragma unroll 8
    for (int k = 0; k < P; k++) {
        float4 b = Wsm4[k * 128 + tx];
#pragma unroll
        for (int rr = 0; rr < 12; rr++) {
            float a = xrs[aoff[rr] + k];
            acc[rr].x = fmaf(a, b.x, acc[rr].x);
            acc[rr].y = fmaf(a, b.y, acc[rr].y);
            acc[rr].z = fmaf(a, b.z, acc[rr].z);
            acc[rr].w = fmaf(a, b.w, acc[rr].w);
        }
    }

    const float4* pe4 = (const float4*)g_pe;
#pragma unroll
    for (int rr = 0; rr < 12; rr++) {
        int row = ty * 12 + rr;
        int reg = row / U;
        int q   = row % U;                 // compile-time (12 % U == 0)
        if (reg >= nval) break;
        int rid = rids[reg];
        int n = rid / 7, r = rid - n * 7;
        constexpr int TB_MAX = 6;
#pragma unroll
        for (int t = q * K; t < ((q + 1) * K < TB_MAX ? (q + 1) * K : TB_MAX); t++) {
            int pos = r * 6 + t;
            float4 p = pe4[pos * 128 + tx];
            float4 v;
            v.x = acc[rr].x + p.x; v.y = acc[rr].y + p.y;
            v.z = acc[rr].z + p.z; v.w = acc[rr].w + p.w;
            out4[(long long)n * 5376 + pos * 128 + tx] = v;
        }
    }
}

// --------------------------- launch ------------------------------------------
extern "C" void kernel_launch(void* const* d_in, const int* in_sizes, int n_in,
                              void* d_out, int out_size) {
    const float* x  = (const float*)d_in[0];
    const float* un = (const float*)d_in[1];
    const float* W1 = (const float*)d_in[2];
    const float* b1 = (const float*)d_in[3];
    const float* W2 = (const float*)d_in[4];
    const float* b2 = (const float*)d_in[5];
    const float4* We0 = (const float4*)d_in[6];
    const float4* We1 = (const float4*)d_in[7];
    const float4* We2 = (const float4*)d_in[8];
    const float4* We3 = (const float4*)d_in[9];
    float*  out  = (float*)d_out;
    float4* out4 = (float4*)d_out;
    const float4* x4 = (const float4*)d_in[0];

    int write_mode = 0;
    if ((long long)out_size >= XP_ELEMS + 1 + 28672) write_mode = 2;
    else if ((long long)out_size >= XP_ELEMS + 1)    write_mode = 1;

    // dynamic smem: P*512*4 (weights) + RPB*48*4 (xr)
    const int S8  =  8 * 512 * 4 +  4 * 48 * 4;   // 17152
    const int S16 = 16 * 512 * 4 + 12 * 48 * 4;   // 35072
    const int S24 = 24 * 512 * 4 + 12 * 48 * 4;   // 51456
    const int S48 = 48 * 512 * 4 + 24 * 48 * 4;   // 102912
    cudaFuncSetAttribute(embed_kernel<24>, cudaFuncAttributeMaxDynamicSharedMemorySize, S24);
    cudaFuncSetAttribute(embed_kernel<48>, cudaFuncAttributeMaxDynamicSharedMemorySize, S48);

    pe_init_kernel<<<84, 256>>>();
    router_kernel<<<112, 256>>>(x, un, W1, b1, W2, b2, out, write_mode);
    embed_kernel<8> <<<7168, 256, S8 >>>(x4, We0, out4);   // RPB=4
    embed_kernel<16><<<2390, 256, S16>>>(x4, We1, out4);   // RPB=12
    embed_kernel<24><<<2390, 256, S24>>>(x4, We2, out4);   // RPB=12
    embed_kernel<48><<<1195, 256, S48>>>(x4, We3, out4);   // RPB=24
    (void)in_sizes; (void)n_in;
}

// round 2
// speedup vs baseline: 1.4869x; 1.4869x over previous
#include <cuda_runtime.h>
#include <math.h>

// ---------------------------------------------------------------------------
// AdaptivePatchEmbedding — B=128,C=32,S=336 -> N=4096, R=7, TARGET=6, D=512
// Straight-through gumbel == one-hot: compute only selected expert per region.
// Unique patch rows per region: P=8 ->6, P=16/24 ->2, P=48 ->1.
// Pipeline: pe_init -> router (compaction) -> ONE persistent fused embed.
// ---------------------------------------------------------------------------

#define NREG 28672            // 4096 * 7
#define XP_ELEMS 88080384LL   // 4096 * 42 * 512

__device__ int   g_counts[4];
__device__ int   g_cursor[4];
__device__ int   g_lists[4 * NREG];
__device__ float g_pe[42 * 512];

// --------------------------- stage 0: pe table + counter reset --------------
__global__ void __launch_bounds__(256) pe_init_kernel() {
    int i = blockIdx.x * 256 + threadIdx.x;
    if (i < 4) { g_counts[i] = 0; g_cursor[i] = 0; }
    if (i < 42 * 512) {
        int pos = i >> 9;
        int d   = i & 511;
        double dv  = exp((double)(d & ~1) * -(log(10000.0) / 512.0));
        float ang  = (float)((double)pos * dv);
        g_pe[i] = (d & 1) ? cosf(ang) : sinf(ang);
    }
}

// --------------------------- stage 1: router --------------------------------
__global__ void __launch_bounds__(64) router_kernel(
    const float* __restrict__ x,  const float* __restrict__ un,
    const float* __restrict__ W1, const float* __restrict__ b1,
    const float* __restrict__ W2, const float* __restrict__ b2,
    float* __restrict__ out, int write_mode)
{
    __shared__ float W1s[48 * 64];
    __shared__ float W2s[256];
    __shared__ float b1s[64];
    int tid = threadIdx.x;
    for (int i = tid; i < 768; i += 64) ((float4*)W1s)[i] = ((const float4*)W1)[i];
    ((float4*)W2s)[tid] = ((const float4*)W2)[tid];
    b1s[tid] = b1[tid];
    __syncthreads();

    int region = blockIdx.x * 64 + tid;      // grid = 448 -> exactly 28672
    int n = region / 7, r = region - n * 7;

    float xr[48];
    const float4* xp = (const float4*)x + n * 84 + r * 12;
#pragma unroll
    for (int v = 0; v < 12; v++) {
        float4 t = xp[v];
        xr[4*v+0] = t.x; xr[4*v+1] = t.y; xr[4*v+2] = t.z; xr[4*v+3] = t.w;
    }

    float lg0 = b2[0], lg1 = b2[1], lg2 = b2[2], lg3 = b2[3];
#pragma unroll 2
    for (int k = 0; k < 64; k++) {
        float s = b1s[k];
#pragma unroll
        for (int j = 0; j < 48; j++) s = fmaf(xr[j], W1s[j * 64 + k], s);
        s = fmaxf(s, 0.0f);
        lg0 = fmaf(s, W2s[k*4+0], lg0);
        lg1 = fmaf(s, W2s[k*4+1], lg1);
        lg2 = fmaf(s, W2s[k*4+2], lg2);
        lg3 = fmaf(s, W2s[k*4+3], lg3);
    }

    const float* up = un + (long long)region * 4;
    float z0 = lg0 - logf(-logf(up[0] + 1e-10f) + 1e-10f);
    float z1 = lg1 - logf(-logf(up[1] + 1e-10f) + 1e-10f);
    float z2 = lg2 - logf(-logf(up[2] + 1e-10f) + 1e-10f);
    float z3 = lg3 - logf(-logf(up[3] + 1e-10f) + 1e-10f);

    int e = 0; float best = z0;              // first-max semantics like jnp.argmax
    if (z1 > best) { best = z1; e = 1; }
    if (z2 > best) { best = z2; e = 2; }
    if (z3 > best) { best = z3; e = 3; }

    int slot = atomicAdd(&g_counts[e], 1);
    g_lists[e * NREG + slot] = region;

    if (write_mode >= 2) out[XP_ELEMS + 1 + (long long)r * 4096 + n] = (float)e;
    if (write_mode >= 1 && region == 0) out[XP_ELEMS] = 32.0f;
}

// --------------------------- stage 2: persistent fused embed ----------------
// 12 unique rows per chunk; thread (tx in [0,128), ty in {0,1}) owns 6 rows x 4 cols.
// For P: K = 7-48/P repeats per unique row, U = ceil(6/K) unique rows/region,
// RPB = 12/U regions per chunk. Work dealt via per-expert atomic cursors.
template<int P, bool WSM>
__device__ __forceinline__ void embed_expert(
    const float4* __restrict__ x4, const float4* __restrict__ W4,
    float4* __restrict__ out4, float* Wsm, float* xrs, int* ibuf)
{
    constexpr int E   = (P == 8) ? 0 : (P == 16) ? 1 : (P == 24) ? 2 : 3;
    constexpr int K   = 7 - 48 / P;
    constexpr int U   = (6 + K - 1) / K;
    constexpr int RPB = 12 / U;

    const int tid = threadIdx.x;
    const int cnt = g_counts[E];

    if (WSM) {
        for (int i = tid; i < P * 128; i += 256)
            ((float4*)Wsm)[i] = W4[i];
    }
    const int tx = tid & 127, ty = tid >> 7;

    int aoff[6];
#pragma unroll
    for (int rr = 0; rr < 6; rr++) {
        int row = ty * 6 + rr;
        aoff[rr] = (row / U) * 48 + (row % U) * P;
    }

    for (;;) {
        if (tid == 0) ibuf[15] = atomicAdd(&g_cursor[E], 1);
        __syncthreads();
        int base = ibuf[15] * RPB;
        if (base >= cnt) break;
        int nval = min(RPB, cnt - base);
        if (tid < nval) ibuf[tid] = g_lists[E * NREG + base + tid];
        __syncthreads();

        for (int i = tid; i < nval * 12; i += 256) {
            int reg = i / 12, v = i - reg * 12;
            int rid = ibuf[reg];
            int n = rid / 7, r = rid - n * 7;
            ((float4*)xrs)[reg * 12 + v] = __ldg(&x4[n * 84 + r * 12 + v]);
        }
        __syncthreads();

        float4 acc[6];
#pragma unroll
        for (int i = 0; i < 6; i++) acc[i] = make_float4(0.f, 0.f, 0.f, 0.f);

#pragma unroll
        for (int k = 0; k < P; k += 2) {
            float4 b0 = WSM ? ((const float4*)Wsm)[k * 128 + tx]
                            : __ldg(&W4[k * 128 + tx]);
            float4 b1 = WSM ? ((const float4*)Wsm)[(k + 1) * 128 + tx]
                            : __ldg(&W4[(k + 1) * 128 + tx]);
#pragma unroll
            for (int rr = 0; rr < 6; rr++) {
                float2 a = *(const float2*)&xrs[aoff[rr] + k];
                acc[rr].x = fmaf(a.x, b0.x, acc[rr].x);
                acc[rr].y = fmaf(a.x, b0.y, acc[rr].y);
                acc[rr].z = fmaf(a.x, b0.z, acc[rr].z);
                acc[rr].w = fmaf(a.x, b0.w, acc[rr].w);
                acc[rr].x = fmaf(a.y, b1.x, acc[rr].x);
                acc[rr].y = fmaf(a.y, b1.y, acc[rr].y);
                acc[rr].z = fmaf(a.y, b1.z, acc[rr].z);
                acc[rr].w = fmaf(a.y, b1.w, acc[rr].w);
            }
        }

        const float4* pe4 = (const float4*)g_pe;
#pragma unroll
        for (int rr = 0; rr < 6; rr++) {
            int row = ty * 6 + rr;
            int reg = row / U;
            int q   = row % U;
            if (reg >= nval) continue;
            int rid = ibuf[reg];
            int n = rid / 7, r = rid - n * 7;
#pragma unroll
            for (int t = q * K; t < ((q + 1) * K < 6 ? (q + 1) * K : 6); t++) {
                int pos = r * 6 + t;
                float4 p = __ldg(&pe4[pos * 128 + tx]);
                float4 v = make_float4(acc[rr].x + p.x, acc[rr].y + p.y,
                                       acc[rr].z + p.z, acc[rr].w + p.w);
                __stcs(&out4[(long long)n * 5376 + pos * 128 + tx], v);
            }
        }
        __syncthreads();
    }
    __syncthreads();   // all threads done with ibuf before next expert reuses it
}

__global__ void __launch_bounds__(256, 4) embed_fused_kernel(
    const float4* __restrict__ x4,
    const float4* __restrict__ We0, const float4* __restrict__ We1,
    const float4* __restrict__ We2, const float4* __restrict__ We3,
    float4* __restrict__ out4)
{
    extern __shared__ float sm[];
    float* Wsm = sm;                       // up to 24*512 floats
    float* xrs = sm + 24 * 512;            // 12*48 floats
    int*   ibuf = (int*)(xrs + 12 * 48);   // 16 ints

    embed_expert<48, false>(x4, We3, out4, Wsm, xrs, ibuf);
    embed_expert<24, true >(x4, We2, out4, Wsm, xrs, ibuf);
    embed_expert<16, true >(x4, We1, out4, Wsm, xrs, ibuf);
    embed_expert< 8, true >(x4, We0, out4, Wsm, xrs, ibuf);
}

// --------------------------- launch ------------------------------------------
extern "C" void kernel_launch(void* const* d_in, const int* in_sizes, int n_in,
                              void* d_out, int out_size) {
    const float* x  = (const float*)d_in[0];
    const float* un = (const float*)d_in[1];
    const float* W1 = (const float*)d_in[2];
    const float* b1 = (const float*)d_in[3];
    const float* W2 = (const float*)d_in[4];
    const float* b2 = (const float*)d_in[5];
    const float4* We0 = (const float4*)d_in[6];
    const float4* We1 = (const float4*)d_in[7];
    const float4* We2 = (const float4*)d_in[8];
    const float4* We3 = (const float4*)d_in[9];
    float*  out  = (float*)d_out;
    float4* out4 = (float4*)d_out;
    const float4* x4 = (const float4*)d_in[0];

    int write_mode = 0;
    if ((long long)out_size >= XP_ELEMS + 1 + 28672) write_mode = 2;
    else if ((long long)out_size >= XP_ELEMS + 1)    write_mode = 1;

    const int SMEM = (24 * 512 + 12 * 48) * 4 + 64;   // 51520 bytes
    cudaFuncSetAttribute(embed_fused_kernel,
                         cudaFuncAttributeMaxDynamicSharedMemorySize, SMEM);

    pe_init_kernel<<<84, 256>>>();
    router_kernel<<<448, 64>>>(x, un, W1, b1, W2, b2, out, write_mode);
    embed_fused_kernel<<<592, 256, SMEM>>>(x4, We0, We1, We2, We3, out4);
    (void)in_sizes; (void)n_in;
}